// round 6
// baseline (speedup 1.0000x reference)
#include <cuda_runtime.h>
#include <math.h>

typedef unsigned long long u64;

#define C_DIM 2048
#define E_DIM 64
#define TM    128
#define KT    16
#define NTHR  256
#define NKT   (C_DIM / KT)
#define ASTR  132            // floats per k-row of As (pad for STS conflicts)
#define BSTR  144            // floats per k-row of duplicated B (group-padded)
#define AMB_CAP 65536
#define TAU   1e-5f

__device__ float g_colsq[E_DIM];
__device__ unsigned g_amb_count;
__device__ unsigned g_amb_list[AMB_CAP];

__device__ __forceinline__ void fma2(u64& d, u64 a, u64 b) {
    asm("fma.rn.f32x2 %0, %1, %2, %0;" : "+l"(d) : "l"(a), "l"(b));
}
__device__ __forceinline__ float lo32(u64 v) { return __uint_as_float((unsigned)v); }
__device__ __forceinline__ float hi32(u64 v) { return __uint_as_float((unsigned)(v >> 32)); }

// ---------------------------------------------------------------------------
// Kernel 0: reset accumulators.
// ---------------------------------------------------------------------------
__global__ void zero_kernel() {
    if (threadIdx.x < E_DIM) g_colsq[threadIdx.x] = 0.f;
    if (threadIdx.x == 0) g_amb_count = 0;
}

// ---------------------------------------------------------------------------
// Kernel 1: coalesced column sum-of-squares of sim (C x E), atomic per block.
// 64 blocks x 256 threads; block b covers rows [32b, 32b+32).
// ---------------------------------------------------------------------------
__global__ void colsum_kernel(const float* __restrict__ sim) {
    __shared__ float part[4][E_DIM];
    const int col = threadIdx.x & 63;
    const int rg  = threadIdx.x >> 6;         // 0..3
    const int base = blockIdx.x * 32;
    float s = 0.f;
#pragma unroll
    for (int j = 0; j < 8; ++j) {
        float v = sim[(size_t)(base + rg + j * 4) * E_DIM + col];
        s = fmaf(v, v, s);
    }
    part[rg][col] = s;
    __syncthreads();
    if (threadIdx.x < E_DIM) {
        float t = part[0][threadIdx.x] + part[1][threadIdx.x]
                + part[2][threadIdx.x] + part[3][threadIdx.x];
        atomicAdd(&g_colsq[threadIdx.x], t);
    }
}

// ---------------------------------------------------------------------------
// Kernel 2: fused gating GEMM. 128x64 tile, 256 threads, 8x4 micro-tile as
// packed f32x2 accumulators. Warp-specialized loaders, double-buffered smem
// (one sync/tile), pre-duplicated B (no pack MOVs in inner loop),
// register/shuffle epilogue.
// ---------------------------------------------------------------------------
__global__ __launch_bounds__(NTHR)
void gating_kernel(const float* __restrict__ x,
                   const float* __restrict__ sim,
                   const float* __restrict__ gates,
                   const float* __restrict__ temp,
                   const float* __restrict__ emask,
                   const int*   __restrict__ minkp,
                   float* __restrict__ out,
                   int N)
{
    __shared__ float As[2][KT][ASTR];        // [buf][k][row]
    __shared__ float Bs[2][KT][BSTR];        // [buf][k][dup-col, group-padded]
    __shared__ float rowinvS[TM];

    const int tid  = threadIdx.x;
    const int row0 = blockIdx.x * TM;
    const bool isA = tid < 128;

    // A loader: one thread per row, 16 floats (4 x float4) per tile.
    const int arow = tid;                                        // if isA
    const float* aptr = x + (size_t)min(row0 + arow, N - 1) * C_DIM;

    // B loader: 128 threads; thread covers (k-row kB, 8 cols starting 8*gg).
    const int bi = tid - 128;
    const int kB = bi >> 3;
    const int gg = bi & 7;
    const float* bptr = sim + (size_t)kB * E_DIM + gg * 8;
    // duplicated-store offsets for groups 2gg, 2gg+1 (8 floats + pad/4 groups)
    const int bg0 = (2 * gg)     * 8 + (((2 * gg))     >> 2) * 4;
    const int bg1 = (2 * gg + 1) * 8 + (((2 * gg + 1)) >> 2) * 4;

    // compute mapping: tx = col group (4 cols), ty = row group (8 rows)
    const int tx = tid & 15;
    const int ty = tid >> 4;
    const int brd = tx * 8 + (tx >> 2) * 4;  // dup-B read offset (floats)

    u64 acc[4][4];
#pragma unroll
    for (int i = 0; i < 4; ++i)
#pragma unroll
        for (int j = 0; j < 4; ++j) acc[i][j] = 0ull;

    float4 a0, a1, a2, a3;                   // A stage regs
    float4 b0, b1;                           // B stage regs
    float sumsq = 0.f;

    // prologue: load tile 0
    if (isA) {
        a0 = *(const float4*)(aptr);
        a1 = *(const float4*)(aptr + 4);
        a2 = *(const float4*)(aptr + 8);
        a3 = *(const float4*)(aptr + 12);
    } else {
        b0 = *(const float4*)(bptr);
        b1 = *(const float4*)(bptr + 4);
    }

#pragma unroll 1
    for (int kt = 0; kt < NKT; ++kt) {
        const int cur = kt & 1;
        // store staged tile into buf cur
        if (isA) {
            As[cur][ 0][arow] = a0.x; As[cur][ 1][arow] = a0.y;
            As[cur][ 2][arow] = a0.z; As[cur][ 3][arow] = a0.w;
            As[cur][ 4][arow] = a1.x; As[cur][ 5][arow] = a1.y;
            As[cur][ 6][arow] = a1.z; As[cur][ 7][arow] = a1.w;
            As[cur][ 8][arow] = a2.x; As[cur][ 9][arow] = a2.y;
            As[cur][10][arow] = a2.z; As[cur][11][arow] = a2.w;
            As[cur][12][arow] = a3.x; As[cur][13][arow] = a3.y;
            As[cur][14][arow] = a3.z; As[cur][15][arow] = a3.w;
            sumsq = fmaf(a0.x, a0.x, sumsq); sumsq = fmaf(a0.y, a0.y, sumsq);
            sumsq = fmaf(a0.z, a0.z, sumsq); sumsq = fmaf(a0.w, a0.w, sumsq);
            sumsq = fmaf(a1.x, a1.x, sumsq); sumsq = fmaf(a1.y, a1.y, sumsq);
            sumsq = fmaf(a1.z, a1.z, sumsq); sumsq = fmaf(a1.w, a1.w, sumsq);
            sumsq = fmaf(a2.x, a2.x, sumsq); sumsq = fmaf(a2.y, a2.y, sumsq);
            sumsq = fmaf(a2.z, a2.z, sumsq); sumsq = fmaf(a2.w, a2.w, sumsq);
            sumsq = fmaf(a3.x, a3.x, sumsq); sumsq = fmaf(a3.y, a3.y, sumsq);
            sumsq = fmaf(a3.z, a3.z, sumsq); sumsq = fmaf(a3.w, a3.w, sumsq);
        } else {
            float2* p0 = (float2*)&Bs[cur][kB][bg0];
            p0[0] = make_float2(b0.x, b0.x); p0[1] = make_float2(b0.y, b0.y);
            p0[2] = make_float2(b0.z, b0.z); p0[3] = make_float2(b0.w, b0.w);
            float2* p1 = (float2*)&Bs[cur][kB][bg1];
            p1[0] = make_float2(b1.x, b1.x); p1[1] = make_float2(b1.y, b1.y);
            p1[2] = make_float2(b1.z, b1.z); p1[3] = make_float2(b1.w, b1.w);
        }
        __syncthreads();                      // tile cur visible

        // prefetch next tile into regs (latency hidden under compute)
        if (kt + 1 < NKT) {
            if (isA) {
                const float* p = aptr + (kt + 1) * KT;
                a0 = *(const float4*)(p);
                a1 = *(const float4*)(p + 4);
                a2 = *(const float4*)(p + 8);
                a3 = *(const float4*)(p + 12);
            } else {
                const float* p = bptr + (size_t)(kt + 1) * KT * E_DIM;
                b0 = *(const float4*)(p);
                b1 = *(const float4*)(p + 4);
            }
        }

#pragma unroll
        for (int k = 0; k < KT; ++k) {
            ulonglong2 aL = *(const ulonglong2*)&As[cur][k][ty * 8];
            ulonglong2 aH = *(const ulonglong2*)&As[cur][k][ty * 8 + 4];
            ulonglong2 bA = *(const ulonglong2*)&Bs[cur][k][brd];
            ulonglong2 bB = *(const ulonglong2*)&Bs[cur][k][brd + 4];
            fma2(acc[0][0], aL.x, bA.x); fma2(acc[0][1], aL.x, bA.y);
            fma2(acc[0][2], aL.x, bB.x); fma2(acc[0][3], aL.x, bB.y);
            fma2(acc[1][0], aL.y, bA.x); fma2(acc[1][1], aL.y, bA.y);
            fma2(acc[1][2], aL.y, bB.x); fma2(acc[1][3], aL.y, bB.y);
            fma2(acc[2][0], aH.x, bA.x); fma2(acc[2][1], aH.x, bA.y);
            fma2(acc[2][2], aH.x, bB.x); fma2(acc[2][3], aH.x, bB.y);
            fma2(acc[3][0], aH.y, bA.x); fma2(acc[3][1], aH.y, bA.y);
            fma2(acc[3][2], aH.y, bB.x); fma2(acc[3][3], aH.y, bB.y);
        }
        __syncthreads();                      // done reading buf cur
    }

    // row inverse norms
    if (isA) rowinvS[arow] = 1.0f / fmaxf(sqrtf(sumsq), 1e-12f);
    __syncthreads();

    // per-column constants for this thread's 4 columns
    float cf[4], gth[4];
    {
        float t = temp[0];
        float scale = 1.0f / (1.0f + expf(-t));
#pragma unroll
        for (int c = 0; c < 4; ++c) {
            int col = tx * 4 + c;
            float ci = 1.0f / fmaxf(sqrtf(g_colsq[col]), 1e-12f);
            cf[c]  = ci * emask[col];
            gth[c] = gates[col] * scale;
        }
    }
    int minK = minkp ? *minkp : 2;
    minK = min(max(minK, 0), E_DIM);

    const size_t NE = (size_t)N * E_DIM;

#pragma unroll
    for (int rp = 0; rp < 4; ++rp) {
#pragma unroll
        for (int h = 0; h < 2; ++h) {
            const int row  = ty * 8 + rp * 2 + h;
            const int grow = row0 + row;
            const float ri = rowinvS[row];
            float lg[4], m[4];
            float cnt = 0.f;
#pragma unroll
            for (int c = 0; c < 4; ++c) {
                float raw = h ? hi32(acc[rp][c]) : lo32(acc[rp][c]);
                lg[c] = raw * ri * cf[c];
                float z = lg[c] - gth[c];
                m[c] = (z > 0.f) ? 1.0f : 0.0f;
                cnt += m[c];
                if (fabsf(z) < TAU && grow < N) {
                    unsigned idx = atomicAdd(&g_amb_count, 1u);
                    if (idx < AMB_CAP)
                        g_amb_list[idx] = ((unsigned)grow << 8)
                                        | (unsigned)(tx * 4 + c);
                }
            }
            // half-warp (16 lanes share a row) count reduce
#pragma unroll
            for (int o = 8; o; o >>= 1)
                cnt += __shfl_xor_sync(0xffffffffu, cnt, o);

            if (cnt == 0.f) {                 // fallback top-minK (cold path)
                for (int kk = 0; kk < minK; ++kk) {
                    float bv = -3.402823466e38f;
                    int   gc = 1 << 20;
#pragma unroll
                    for (int c = 0; c < 4; ++c) {
                        if (m[c] == 0.f && lg[c] > bv) {
                            bv = lg[c];
                            gc = tx * 4 + c;
                        }
                    }
#pragma unroll
                    for (int o = 8; o; o >>= 1) {
                        float ov = __shfl_xor_sync(0xffffffffu, bv, o);
                        int   oi = __shfl_xor_sync(0xffffffffu, gc, o);
                        if (ov > bv || (ov == bv && oi < gc)) { bv = ov; gc = oi; }
                    }
                    if ((gc >> 2) == tx) m[gc & 3] = 1.0f;
                }
            }

            if (grow < N) {
                *(float4*)&out[(size_t)grow * E_DIM + tx * 4] =
                    make_float4(m[0], m[1], m[2], m[3]);
                *(float4*)&out[NE + (size_t)grow * E_DIM + tx * 4] =
                    make_float4(lg[0], lg[1], lg[2], lg[3]);
            }
        }
    }
}

// ---------------------------------------------------------------------------
// Kernel 3: fp64 refinement of ambiguous mask entries. One warp per entry.
// ---------------------------------------------------------------------------
__global__ __launch_bounds__(128)
void refine_kernel(const float* __restrict__ x,
                   const float* __restrict__ sim,
                   const float* __restrict__ gates,
                   const float* __restrict__ temp,
                   const float* __restrict__ emask,
                   float* __restrict__ out)
{
    unsigned cnt = g_amb_count;
    if (cnt > AMB_CAP) cnt = AMB_CAP;
    const int lane  = threadIdx.x & 31;
    const int warp  = (blockIdx.x * blockDim.x + threadIdx.x) >> 5;
    const int nwarp = (gridDim.x * blockDim.x) >> 5;

    for (unsigned i = warp; i < cnt; i += nwarp) {
        unsigned pk = g_amb_list[i];
        int r = (int)(pk >> 8);
        int e = (int)(pk & 0xFF);
        const float* ar = x + (size_t)r * C_DIM;
        double d = 0.0, na = 0.0, nb = 0.0;
        for (int k = lane; k < C_DIM; k += 32) {
            double av = (double)ar[k];
            double bv = (double)sim[(size_t)k * E_DIM + e];
            d  = fma(av, bv, d);
            na = fma(av, av, na);
            nb = fma(bv, bv, nb);
        }
#pragma unroll
        for (int off = 16; off; off >>= 1) {
            d  += __shfl_xor_sync(0xffffffffu, d,  off);
            na += __shfl_xor_sync(0xffffffffu, na, off);
            nb += __shfl_xor_sync(0xffffffffu, nb, off);
        }
        if (lane == 0) {
            double t     = (double)temp[0];
            double scale = 1.0 / (1.0 + exp(-t));
            double lgv = d / fmax(sqrt(na), 1e-12) / fmax(sqrt(nb), 1e-12);
            lgv *= (double)emask[e];
            double z = lgv - (double)gates[e] * scale;
            out[(size_t)r * E_DIM + e] = (z > 0.0) ? 1.0f : 0.0f;
        }
    }
}

extern "C" void kernel_launch(void* const* d_in, const int* in_sizes, int n_in,
                              void* d_out, int out_size) {
    (void)out_size;
    const float* x     = (const float*)d_in[0];
    const float* sim   = (const float*)d_in[1];
    const float* gates = (const float*)d_in[2];
    const float* temp  = (const float*)d_in[3];
    const float* emask = (const float*)d_in[4];
    const int*   minkp = (n_in > 5) ? (const int*)d_in[5] : nullptr;

    int N = in_sizes[0] / C_DIM;

    zero_kernel<<<1, 128>>>();
    colsum_kernel<<<C_DIM / 32, 256>>>(sim);
    int grid = (N + TM - 1) / TM;
    gating_kernel<<<grid, NTHR>>>(x, sim, gates, temp, emask, minkp,
                                  (float*)d_out, N);
    refine_kernel<<<128, 128>>>(x, sim, gates, temp, emask, (float*)d_out);
}

// round 9
// speedup vs baseline: 1.3725x; 1.3725x over previous
#include <cuda_runtime.h>
#include <math.h>
#include <stdint.h>

#define C_DIM 2048
#define E_DIM 64
#define TM    64
#define NTHR  128
#define NKT   (C_DIM / 16)      // 128 k16 tiles
#define AMB_CAP 65536
#define TAU   1e-5f

__device__ float    g_colsq[E_DIM];
__device__ unsigned g_amb_count;
__device__ unsigned g_amb_list[AMB_CAP];
// B fragments, packed per k16-tile: [t][j][lane][4] = {hi_w0, hi_w1, lo_w0, lo_w1}
__device__ unsigned g_Bfrag[NKT * 8 * 32 * 4];

// ---------------- helpers ----------------
__device__ __forceinline__ unsigned smem_u32(const void* p) {
    unsigned a;
    asm("{ .reg .u64 t; cvta.to.shared.u64 t, %1; cvt.u32.u64 %0, t; }"
        : "=r"(a) : "l"(p));
    return a;
}
// packs: low half = bf16(lo), high half = bf16(hi)
__device__ __forceinline__ unsigned pack_bf16x2(float lo, float hi) {
    unsigned r;
    asm("cvt.rn.bf16x2.f32 %0, %1, %2;" : "=r"(r) : "f"(hi), "f"(lo));
    return r;
}
__device__ __forceinline__ float lo_f(unsigned u) { return __uint_as_float(u << 16); }
__device__ __forceinline__ float hi_f(unsigned u) { return __uint_as_float(u & 0xFFFF0000u); }

__device__ __forceinline__ void mma16816(float& d0, float& d1, float& d2, float& d3,
                                         unsigned a0, unsigned a1, unsigned a2, unsigned a3,
                                         unsigned b0, unsigned b1) {
    asm volatile(
        "mma.sync.aligned.m16n8k16.row.col.f32.bf16.bf16.f32 "
        "{%0,%1,%2,%3}, {%4,%5,%6,%7}, {%8,%9}, {%0,%1,%2,%3};"
        : "+f"(d0), "+f"(d1), "+f"(d2), "+f"(d3)
        : "r"(a0), "r"(a1), "r"(a2), "r"(a3), "r"(b0), "r"(b1));
}
__device__ __forceinline__ void cp16(unsigned dst, const void* src) {
    asm volatile("cp.async.cg.shared.global [%0], [%1], 16;"
                 :: "r"(dst), "l"(src) : "memory");
}
#define CP_COMMIT() asm volatile("cp.async.commit_group;" ::: "memory")
#define CP_WAIT1()  asm volatile("cp.async.wait_group 1;" ::: "memory")
#define CP_WAIT0()  asm volatile("cp.async.wait_group 0;" ::: "memory")

// ---------------------------------------------------------------------------
// Kernel 0: reset.
// ---------------------------------------------------------------------------
__global__ void zero_kernel() {
    if (threadIdx.x < E_DIM) g_colsq[threadIdx.x] = 0.f;
    if (threadIdx.x == 0) g_amb_count = 0;
}

// ---------------------------------------------------------------------------
// Kernel 1: coalesced column sum-of-squares of sim (C x E).
// ---------------------------------------------------------------------------
__global__ void colsum_kernel(const float* __restrict__ sim) {
    __shared__ float part[4][E_DIM];
    const int col  = threadIdx.x & 63;
    const int rg   = threadIdx.x >> 6;
    const int base = blockIdx.x * 32;
    float s = 0.f;
#pragma unroll
    for (int j = 0; j < 8; ++j) {
        float v = sim[(size_t)(base + rg + j * 4) * E_DIM + col];
        s = fmaf(v, v, s);
    }
    part[rg][col] = s;
    __syncthreads();
    if (threadIdx.x < E_DIM) {
        float t = part[0][threadIdx.x] + part[1][threadIdx.x]
                + part[2][threadIdx.x] + part[3][threadIdx.x];
        atomicAdd(&g_colsq[threadIdx.x], t);
    }
}

// ---------------------------------------------------------------------------
// Kernel 2: pack B (sim) into mma.sync col-major fragments, bf16 hi/lo split.
// One thread per (k16-tile t, lane l); 4096 threads.
// b-frag word w0 = {B[k0][n], B[k0+1][n]}, w1 = {B[k0+8][n], B[k0+9][n]},
// k0 = t*16 + (l&3)*2, n = j*8 + (l>>2).
// ---------------------------------------------------------------------------
__global__ void prepb_kernel(const float* __restrict__ sim) {
    int tid = blockIdx.x * 256 + threadIdx.x;
    int t = tid >> 5, l = tid & 31;
    int k0 = t * 16 + (l & 3) * 2;
    int nb = l >> 2;
#pragma unroll
    for (int j = 0; j < 8; ++j) {
        int n = j * 8 + nb;
        float x0 = sim[(size_t)k0 * E_DIM + n];
        float x1 = sim[(size_t)(k0 + 1) * E_DIM + n];
        float y0 = sim[(size_t)(k0 + 8) * E_DIM + n];
        float y1 = sim[(size_t)(k0 + 9) * E_DIM + n];
        unsigned h0 = pack_bf16x2(x0, x1);
        unsigned h1 = pack_bf16x2(y0, y1);
        unsigned l0 = pack_bf16x2(x0 - lo_f(h0), x1 - hi_f(h0));
        unsigned l1 = pack_bf16x2(y0 - lo_f(h1), y1 - hi_f(h1));
        unsigned* dst = g_Bfrag + ((size_t)(t * 8 + j) * 32 + l) * 4;
        dst[0] = h0; dst[1] = h1; dst[2] = l0; dst[3] = l1;
    }
}

// ---------------------------------------------------------------------------
// Kernel 3: gating GEMM via mma.sync bf16 3-pass split.
// CTA: 64 rows x 64 experts, 4 warps; warp w owns rows [w*16, w*16+16).
// A: gmem->reg fp32, converted per-thread (read exactly once).
// B: cp.async gmem->smem (4KB/tile), double buffered.
// ---------------------------------------------------------------------------
__global__ __launch_bounds__(NTHR)
void gating_kernel(const float* __restrict__ x,
                   const float* __restrict__ gates,
                   const float* __restrict__ temp,
                   const float* __restrict__ emask,
                   float* __restrict__ out,
                   int N)
{
    __shared__ __align__(16) unsigned Bs[2][8 * 32 * 4];
    __shared__ float Lg[TM][E_DIM + 4];
    __shared__ float rowinvS[TM];
    __shared__ float cfS[E_DIM], gthS[E_DIM];

    const int tid  = threadIdx.x;
    const int wid  = tid >> 5;
    const int lane = tid & 31;
    const int row0 = blockIdx.x * TM;

    if (tid < E_DIM) {
        cfS[tid]  = (1.0f / fmaxf(sqrtf(g_colsq[tid]), 1e-12f)) * emask[tid];
        gthS[tid] = gates[tid] * (1.0f / (1.0f + expf(-temp[0])));
    }

    const int gr = lane >> 2;            // fragment row within 8
    const int gq = (lane & 3) * 2;       // fragment k/col pair base
    const int r0g = min(row0 + wid * 16 + gr,     N - 1);
    const int r8g = min(row0 + wid * 16 + gr + 8, N - 1);
    const float* aptr0 = x + (size_t)r0g * C_DIM + gq;
    const float* aptr8 = x + (size_t)r8g * C_DIM + gq;

    const unsigned sB[2] = { smem_u32(&Bs[0][0]) + (unsigned)tid * 32,
                             smem_u32(&Bs[1][0]) + (unsigned)tid * 32 };
    const unsigned* bsrc = g_Bfrag + tid * 8;

    float acc[8][4];
#pragma unroll
    for (int j = 0; j < 8; ++j)
#pragma unroll
        for (int c = 0; c < 4; ++c) acc[j][c] = 0.f;

    // prologue: B tile 0 + A tile 0
    cp16(sB[0], bsrc); cp16(sB[0] + 16, bsrc + 4);
    CP_COMMIT();
    float2 p00 = *(const float2*)(aptr0);
    float2 p01 = *(const float2*)(aptr0 + 8);
    float2 p10 = *(const float2*)(aptr8);
    float2 p11 = *(const float2*)(aptr8 + 8);
    float ssa = 0.f, ssb = 0.f;

#pragma unroll 1
    for (int t = 0; t < NKT; ++t) {
        const int cur = t & 1;
        float2 q00, q01, q10, q11;
        if (t + 1 < NKT) {
            const unsigned* bs = bsrc + (size_t)(t + 1) * 1024;
            cp16(sB[cur ^ 1], bs); cp16(sB[cur ^ 1] + 16, bs + 4);
            CP_COMMIT();
            const float* a0 = aptr0 + (t + 1) * 16;
            const float* a8 = aptr8 + (t + 1) * 16;
            q00 = *(const float2*)(a0); q01 = *(const float2*)(a0 + 8);
            q10 = *(const float2*)(a8); q11 = *(const float2*)(a8 + 8);
        }

        // convert A(t): bf16 hi/lo, fused row sumsq
        ssa = fmaf(p00.x, p00.x, ssa); ssa = fmaf(p00.y, p00.y, ssa);
        ssa = fmaf(p01.x, p01.x, ssa); ssa = fmaf(p01.y, p01.y, ssa);
        ssb = fmaf(p10.x, p10.x, ssb); ssb = fmaf(p10.y, p10.y, ssb);
        ssb = fmaf(p11.x, p11.x, ssb); ssb = fmaf(p11.y, p11.y, ssb);
        unsigned aH0 = pack_bf16x2(p00.x, p00.y);
        unsigned aH1 = pack_bf16x2(p10.x, p10.y);
        unsigned aH2 = pack_bf16x2(p01.x, p01.y);
        unsigned aH3 = pack_bf16x2(p11.x, p11.y);
        unsigned aL0 = pack_bf16x2(p00.x - lo_f(aH0), p00.y - hi_f(aH0));
        unsigned aL1 = pack_bf16x2(p10.x - lo_f(aH1), p10.y - hi_f(aH1));
        unsigned aL2 = pack_bf16x2(p01.x - lo_f(aH2), p01.y - hi_f(aH2));
        unsigned aL3 = pack_bf16x2(p11.x - lo_f(aH3), p11.y - hi_f(aH3));

        if (t + 1 < NKT) CP_WAIT1(); else CP_WAIT0();
        __syncthreads();                              // B(t) visible to all

        const uint4* bb = (const uint4*)Bs[cur];
#pragma unroll
        for (int j = 0; j < 8; ++j) {
            uint4 b = bb[j * 32 + lane];
            mma16816(acc[j][0], acc[j][1], acc[j][2], acc[j][3],
                     aH0, aH1, aH2, aH3, b.x, b.y);   // hi * Bhi
            mma16816(acc[j][0], acc[j][1], acc[j][2], acc[j][3],
                     aH0, aH1, aH2, aH3, b.z, b.w);   // hi * Blo
            mma16816(acc[j][0], acc[j][1], acc[j][2], acc[j][3],
                     aL0, aL1, aL2, aL3, b.x, b.y);   // lo * Bhi
        }
        __syncthreads();                              // buf cur consumed

        p00 = q00; p01 = q01; p10 = q10; p11 = q11;
    }

    // row inverse norms: quad (lane&3) holds partials of rows gr, gr+8
    ssa += __shfl_xor_sync(0xffffffffu, ssa, 1);
    ssa += __shfl_xor_sync(0xffffffffu, ssa, 2);
    ssb += __shfl_xor_sync(0xffffffffu, ssb, 1);
    ssb += __shfl_xor_sync(0xffffffffu, ssb, 2);
    if ((lane & 3) == 0) {
        rowinvS[wid * 16 + gr]     = 1.0f / fmaxf(sqrtf(ssa), 1e-12f);
        rowinvS[wid * 16 + gr + 8] = 1.0f / fmaxf(sqrtf(ssb), 1e-12f);
    }
    __syncthreads();

    const float ri0 = rowinvS[wid * 16 + gr];
    const float ri1 = rowinvS[wid * 16 + gr + 8];
#pragma unroll
    for (int j = 0; j < 8; ++j) {
        int c0 = j * 8 + gq;
        Lg[wid * 16 + gr][c0]         = acc[j][0] * ri0 * cfS[c0];
        Lg[wid * 16 + gr][c0 + 1]     = acc[j][1] * ri0 * cfS[c0 + 1];
        Lg[wid * 16 + gr + 8][c0]     = acc[j][2] * ri1 * cfS[c0];
        Lg[wid * 16 + gr + 8][c0 + 1] = acc[j][3] * ri1 * cfS[c0 + 1];
    }
    __syncthreads();

    // mask + ambiguity flag + coalesced stores
    const size_t NE = (size_t)N * E_DIM;
#pragma unroll
    for (int it = 0; it < (TM * E_DIM) / (4 * NTHR); ++it) {   // 8 iters
        int f4  = tid + it * NTHR;
        int row = f4 >> 4;
        int cc  = (f4 & 15) * 4;
        int grow = row0 + row;
        float lg[4], m[4];
#pragma unroll
        for (int c = 0; c < 4; ++c) {
            lg[c] = Lg[row][cc + c];
            float z = lg[c] - gthS[cc + c];
            m[c] = (z > 0.f) ? 1.0f : 0.0f;
            if (fabsf(z) < TAU && grow < N) {
                unsigned idx = atomicAdd(&g_amb_count, 1u);
                if (idx < AMB_CAP)
                    g_amb_list[idx] = ((unsigned)grow << 8) | (unsigned)(cc + c);
            }
        }
        if (grow < N) {
            *(float4*)&out[(size_t)grow * E_DIM + cc] =
                make_float4(m[0], m[1], m[2], m[3]);
            *(float4*)&out[NE + (size_t)grow * E_DIM + cc] =
                make_float4(lg[0], lg[1], lg[2], lg[3]);
        }
    }
}

// ---------------------------------------------------------------------------
// Kernel 4: fp64 refinement of near-boundary mask entries (x4 ILP).
// ---------------------------------------------------------------------------
__global__ __launch_bounds__(128)
void refine_kernel(const float* __restrict__ x,
                   const float* __restrict__ sim,
                   const float* __restrict__ gates,
                   const float* __restrict__ temp,
                   const float* __restrict__ emask,
                   float* __restrict__ out)
{
    unsigned cnt = g_amb_count;
    if (cnt > AMB_CAP) cnt = AMB_CAP;
    const int lane  = threadIdx.x & 31;
    const int warp  = (blockIdx.x * blockDim.x + threadIdx.x) >> 5;
    const int nwarp = (gridDim.x * blockDim.x) >> 5;

    for (unsigned i = warp; i < cnt; i += nwarp) {
        unsigned pk = g_amb_list[i];
        int rr = (int)(pk >> 8);
        int e  = (int)(pk & 0xFF);
        const float* ar = x + (size_t)rr * C_DIM;
        double d0 = 0, d1 = 0, d2 = 0, d3 = 0;
        double na0 = 0, na1 = 0, na2 = 0, na3 = 0;
        double nb0 = 0, nb1 = 0, nb2 = 0, nb3 = 0;
#pragma unroll 1
        for (int k = lane; k < C_DIM; k += 128) {
            double a0 = ar[k],      b0 = sim[(size_t)(k)      * E_DIM + e];
            double a1 = ar[k + 32], b1 = sim[(size_t)(k + 32) * E_DIM + e];
            double a2 = ar[k + 64], b2 = sim[(size_t)(k + 64) * E_DIM + e];
            double a3 = ar[k + 96], b3 = sim[(size_t)(k + 96) * E_DIM + e];
            d0 = fma(a0, b0, d0); na0 = fma(a0, a0, na0); nb0 = fma(b0, b0, nb0);
            d1 = fma(a1, b1, d1); na1 = fma(a1, a1, na1); nb1 = fma(b1, b1, nb1);
            d2 = fma(a2, b2, d2); na2 = fma(a2, a2, na2); nb2 = fma(b2, b2, nb2);
            d3 = fma(a3, b3, d3); na3 = fma(a3, a3, na3); nb3 = fma(b3, b3, nb3);
        }
        double d  = (d0 + d1) + (d2 + d3);
        double na = (na0 + na1) + (na2 + na3);
        double nb = (nb0 + nb1) + (nb2 + nb3);
#pragma unroll
        for (int off = 16; off; off >>= 1) {
            d  += __shfl_xor_sync(0xffffffffu, d,  off);
            na += __shfl_xor_sync(0xffffffffu, na, off);
            nb += __shfl_xor_sync(0xffffffffu, nb, off);
        }
        if (lane == 0) {
            double t     = (double)temp[0];
            double scale = 1.0 / (1.0 + exp(-t));
            double lgv = d / fmax(sqrt(na), 1e-12) / fmax(sqrt(nb), 1e-12);
            lgv *= (double)emask[e];
            double z = lgv - (double)gates[e] * scale;
            out[(size_t)rr * E_DIM + e] = (z > 0.0) ? 1.0f : 0.0f;
        }
    }
}

// ---------------------------------------------------------------------------
// Kernel 5: fallback top-k. One warp per row; scans FINAL mask (post-refine),
// rows with no active expert get top-minK of logits.
// ---------------------------------------------------------------------------
__global__ __launch_bounds__(256)
void fbfix_kernel(const int* __restrict__ minkp, float* __restrict__ out, int N)
{
    const int lane = threadIdx.x & 31;
    const int row  = (blockIdx.x * blockDim.x + threadIdx.x) >> 5;
    if (row >= N) return;
    float m0 = out[(size_t)row * E_DIM + lane];
    float m1 = out[(size_t)row * E_DIM + 32 + lane];
    unsigned act = __ballot_sync(0xffffffffu, m0 > 0.f)
                 | __ballot_sync(0xffffffffu, m1 > 0.f);
    if (act) return;

    int minK = minkp ? *minkp : 2;
    minK = min(max(minK, 0), E_DIM);
    const size_t NE = (size_t)N * E_DIM;
    float v0 = out[NE + (size_t)row * E_DIM + lane];
    float v1 = out[NE + (size_t)row * E_DIM + 32 + lane];
    bool c0 = false, c1 = false;
    for (int t = 0; t < minK; ++t) {
        float bv = -3.402823466e38f; int bi = 1 << 20;
        if (!c0) { bv = v0; bi = lane; }
        if (!c1 && (v1 > bv || (v1 == bv && lane + 32 < bi))) { bv = v1; bi = lane + 32; }
#pragma unroll
        for (int o = 16; o; o >>= 1) {
            float ov = __shfl_xor_sync(0xffffffffu, bv, o);
            int   oi = __shfl_xor_sync(0xffffffffu, bi, o);
            if (ov > bv || (ov == bv && oi < bi)) { bv = ov; bi = oi; }
        }
        if (bi == lane)      c0 = true;
        if (bi == lane + 32) c1 = true;
        if (lane == 0 && bi < E_DIM)
            out[(size_t)row * E_DIM + bi] = 1.0f;
    }
}

extern "C" void kernel_launch(void* const* d_in, const int* in_sizes, int n_in,
                              void* d_out, int out_size) {
    (void)out_size;
    const float* x     = (const float*)d_in[0];
    const float* sim   = (const float*)d_in[1];
    const float* gates = (const float*)d_in[2];
    const float* temp  = (const float*)d_in[3];
    const float* emask = (const float*)d_in[4];
    const int*   minkp = (n_in > 5) ? (const int*)d_in[5] : nullptr;

    int N = in_sizes[0] / C_DIM;

    zero_kernel<<<1, 128>>>();
    colsum_kernel<<<C_DIM / 32, 256>>>(sim);
    prepb_kernel<<<NKT * 32 / 256, 256>>>(sim);
    gating_kernel<<<(N + TM - 1) / TM, NTHR>>>(x, gates, temp, emask,
                                               (float*)d_out, N);
    refine_kernel<<<128, 128>>>(x, sim, gates, temp, emask, (float*)d_out);
    fbfix_kernel<<<(N * 32 + 255) / 256, 256>>>(minkp, (float*)d_out, N);
}